// round 1
// baseline (speedup 1.0000x reference)
#include <cuda_runtime.h>
#include <cuda_bf16.h>

#define NN 100000
#define NE 800000
#define FIN 256
#define HID 128
#define NCLS 32

// ---------------- scratch (device globals; no allocation allowed) ----------------
__device__ int   g_cnt[NN];
__device__ int   g_rowptr[NN];
__device__ int   g_cursor[NN];
__device__ int   g_part[128];
__device__ float g_dinv[NN];
__device__ int   g_csr[NE];
__device__ int   g_is64;
__device__ __align__(16) float g_xw1[(size_t)NN * HID];   // X @ W1
__device__ __align__(16) float g_h[(size_t)NN * HID];     // relu(agg1)
__device__ __align__(16) float g_xw2[(size_t)NN * NCLS];  // h @ W2

// ---------------- edge index helpers (int32/int64 agnostic) ----------------
__device__ __forceinline__ int load_idx(const void* p, long long i, int is64) {
    if (is64) return (int)((const long long*)p)[i];
    return ((const int*)p)[i];
}

__global__ void k_detect(const void* __restrict__ ei) {
    if (threadIdx.x == 0 && blockIdx.x == 0) {
        const long long* p = (const long long*)ei;
        int ok = 1;
        for (int i = 0; i < 256; i++) {
            long long v = p[i];
            if (v < 0 || v >= NN) { ok = 0; break; }
        }
        g_is64 = ok;
    }
}

__global__ void k_zero(int n) {
    int i = blockIdx.x * blockDim.x + threadIdx.x;
    if (i < n) g_cnt[i] = 0;
}

__global__ void k_hist(const void* __restrict__ ei, int e) {
    int i = blockIdx.x * blockDim.x + threadIdx.x;
    int is64 = g_is64;
    if (i < e) {
        int d = load_idx(ei, (long long)e + i, is64);
        atomicAdd(&g_cnt[d], 1);
    }
}

// ---------------- block exclusive scan ----------------
__device__ __forceinline__ int block_exscan(int v, int* p_total) {
    const int lane = threadIdx.x & 31, w = threadIdx.x >> 5;
    const int nw = blockDim.x >> 5;
    __shared__ int wsum[32];
    int x = v;
#pragma unroll
    for (int o = 1; o < 32; o <<= 1) {
        int y = __shfl_up_sync(0xffffffffu, x, o);
        if (lane >= o) x += y;
    }
    if (lane == 31) wsum[w] = x;
    __syncthreads();
    if (w == 0) {
        int s = (lane < nw) ? wsum[lane] : 0;
#pragma unroll
        for (int o = 1; o < 32; o <<= 1) {
            int y = __shfl_up_sync(0xffffffffu, s, o);
            if (lane >= o) s += y;
        }
        wsum[lane] = s;
    }
    __syncthreads();
    int base = (w > 0) ? wsum[w - 1] : 0;
    *p_total = wsum[31];
    return base + (x - v);
}

__global__ void k_scan1(int n) {
    int i = blockIdx.x * blockDim.x + threadIdx.x;
    int v = (i < n) ? g_cnt[i] : 0;
    int total;
    int ex = block_exscan(v, &total);
    if (i < n) g_rowptr[i] = ex;
    if (threadIdx.x == 0) g_part[blockIdx.x] = total;
}

__global__ void k_scan2(int nb) {
    int i = threadIdx.x;
    int v = (i < nb) ? g_part[i] : 0;
    int total;
    int ex = block_exscan(v, &total);
    if (i < nb) g_part[i] = ex;
}

__global__ void k_scan3(int n) {
    int i = blockIdx.x * blockDim.x + threadIdx.x;
    if (i < n) {
        int rp = g_rowptr[i] + g_part[blockIdx.x];
        g_rowptr[i] = rp;
        g_cursor[i] = rp;
        g_dinv[i] = rsqrtf((float)(g_cnt[i] + 1));  // +1: self loop
    }
}

__global__ void k_scatter(const void* __restrict__ ei, int e) {
    int i = blockIdx.x * blockDim.x + threadIdx.x;
    int is64 = g_is64;
    if (i < e) {
        int s = load_idx(ei, i, is64);
        int d = load_idx(ei, (long long)e + i, is64);
        int pos = atomicAdd(&g_cursor[d], 1);
        g_csr[pos] = s;
    }
}

// ---------------- GEMM1: xw1 = X[100k,256] @ W1[256,128] ----------------
#define G1_BM 64
#define G1_BN 128
#define G1_BK 16

__global__ __launch_bounds__(256) void k_gemm1(const float* __restrict__ X,
                                               const float* __restrict__ W, int n) {
    __shared__ float Xs[G1_BK][G1_BM + 4];  // transposed, padded
    __shared__ float Ws[G1_BK][G1_BN];
    const int tid = threadIdx.x;
    const int row0 = blockIdx.x * G1_BM;
    const int warp = tid >> 5, lane = tid & 31;
    const int wm = warp >> 2, wn = warp & 3;  // 2 x 4 warps
    const int tm = lane >> 3, tn = lane & 7;  // 4 x 8 lanes

    float acc[8][4];
#pragma unroll
    for (int i = 0; i < 8; i++)
#pragma unroll
        for (int j = 0; j < 4; j++) acc[i][j] = 0.f;

    const int ldr = tid >> 2;          // 0..63  (row in tile)
    const int ldk = (tid & 3) * 4;     // 0,4,8,12 (k group)
    int xrow = row0 + ldr; if (xrow >= n) xrow = n - 1;

    for (int k0 = 0; k0 < FIN; k0 += G1_BK) {
        // X tile 64x16 (one float4/thread), stored transposed
        float4 xv = *(const float4*)&X[(long long)xrow * FIN + k0 + ldk];
        Xs[ldk + 0][ldr] = xv.x;
        Xs[ldk + 1][ldr] = xv.y;
        Xs[ldk + 2][ldr] = xv.z;
        Xs[ldk + 3][ldr] = xv.w;
        // W tile 16x128 (two float4/thread)
#pragma unroll
        for (int j = 0; j < 2; j++) {
            int f = tid + j * 256;          // float4 idx 0..511
            int kk = f >> 5, c4 = (f & 31) * 4;
            *(float4*)&Ws[kk][c4] = *(const float4*)&W[(k0 + kk) * G1_BN + c4];
        }
        __syncthreads();
#pragma unroll
        for (int kk = 0; kk < G1_BK; kk++) {
            float4 a0 = *(const float4*)&Xs[kk][wm * 32 + tm * 8];
            float4 a1 = *(const float4*)&Xs[kk][wm * 32 + tm * 8 + 4];
            float4 b  = *(const float4*)&Ws[kk][wn * 32 + tn * 4];
            float av[8] = {a0.x, a0.y, a0.z, a0.w, a1.x, a1.y, a1.z, a1.w};
            float bv[4] = {b.x, b.y, b.z, b.w};
#pragma unroll
            for (int i = 0; i < 8; i++)
#pragma unroll
                for (int j = 0; j < 4; j++) acc[i][j] = fmaf(av[i], bv[j], acc[i][j]);
        }
        __syncthreads();
    }
    const int rbase = row0 + wm * 32 + tm * 8;
    const int col = wn * 32 + tn * 4;
#pragma unroll
    for (int i = 0; i < 8; i++) {
        int r = rbase + i;
        if (r < n)
            *(float4*)&g_xw1[(long long)r * HID + col] =
                make_float4(acc[i][0], acc[i][1], acc[i][2], acc[i][3]);
    }
}

// ---------------- Agg1: h = relu(Ahat @ xw1 + b1), warp per node ----------------
__global__ void k_agg1(const float* __restrict__ b1, int n) {
    int gt = blockIdx.x * blockDim.x + threadIdx.x;
    int node = gt >> 5;
    int lane = threadIdx.x & 31;
    if (node >= n) return;
    int start = g_rowptr[node];
    int cnt = g_cnt[node];
    float di = g_dinv[node];
    const float4* self = (const float4*)&g_xw1[(long long)node * HID];
    float4 v = self[lane];
    float4 acc = make_float4(di * v.x, di * v.y, di * v.z, di * v.w);  // self loop
    for (int e = 0; e < cnt; e++) {
        int s = g_csr[start + e];
        float ds = g_dinv[s];
        float4 w = ((const float4*)&g_xw1[(long long)s * HID])[lane];
        acc.x = fmaf(ds, w.x, acc.x);
        acc.y = fmaf(ds, w.y, acc.y);
        acc.z = fmaf(ds, w.z, acc.z);
        acc.w = fmaf(ds, w.w, acc.w);
    }
    float4 bb = ((const float4*)b1)[lane];
    float4 o;
    o.x = fmaxf(fmaf(di, acc.x, bb.x), 0.f);
    o.y = fmaxf(fmaf(di, acc.y, bb.y), 0.f);
    o.z = fmaxf(fmaf(di, acc.z, bb.z), 0.f);
    o.w = fmaxf(fmaf(di, acc.w, bb.w), 0.f);
    ((float4*)&g_h[(long long)node * HID])[lane] = o;
}

// ---------------- GEMM2: xw2 = h[100k,128] @ W2[128,32] ----------------
#define G2_BM 64
#define G2_BK 16

__global__ __launch_bounds__(256) void k_gemm2(const float* __restrict__ W, int n) {
    __shared__ float Hs[G2_BK][G2_BM + 4];
    __shared__ float Ws[G2_BK][NCLS];
    const int tid = threadIdx.x;
    const int row0 = blockIdx.x * G2_BM;
    const int warp = tid >> 5, lane = tid & 31;  // warp w -> rows w*8..w*8+7, col = lane

    float acc[8];
#pragma unroll
    for (int i = 0; i < 8; i++) acc[i] = 0.f;

    const int ldr = tid >> 2;
    const int ldk = (tid & 3) * 4;
    int hrow = row0 + ldr; if (hrow >= n) hrow = n - 1;

    for (int k0 = 0; k0 < HID; k0 += G2_BK) {
        float4 hv = *(const float4*)&g_h[(long long)hrow * HID + k0 + ldk];
        Hs[ldk + 0][ldr] = hv.x;
        Hs[ldk + 1][ldr] = hv.y;
        Hs[ldk + 2][ldr] = hv.z;
        Hs[ldk + 3][ldr] = hv.w;
        {   // W2 tile 16x32 = 512 floats, one float2/thread
            int kk = tid >> 4, c = (tid & 15) * 2;
            *(float2*)&Ws[kk][c] = *(const float2*)&W[(k0 + kk) * NCLS + c];
        }
        __syncthreads();
#pragma unroll
        for (int kk = 0; kk < G2_BK; kk++) {
            float b = Ws[kk][lane];
            float4 a0 = *(const float4*)&Hs[kk][warp * 8];
            float4 a1 = *(const float4*)&Hs[kk][warp * 8 + 4];
            acc[0] = fmaf(a0.x, b, acc[0]);
            acc[1] = fmaf(a0.y, b, acc[1]);
            acc[2] = fmaf(a0.z, b, acc[2]);
            acc[3] = fmaf(a0.w, b, acc[3]);
            acc[4] = fmaf(a1.x, b, acc[4]);
            acc[5] = fmaf(a1.y, b, acc[5]);
            acc[6] = fmaf(a1.z, b, acc[6]);
            acc[7] = fmaf(a1.w, b, acc[7]);
        }
        __syncthreads();
    }
#pragma unroll
    for (int i = 0; i < 8; i++) {
        int r = row0 + warp * 8 + i;
        if (r < n) g_xw2[(long long)r * NCLS + lane] = acc[i];
    }
}

// ---------------- Agg2 + log_softmax, warp per node ----------------
__global__ void k_agg2(const float* __restrict__ b2, float* __restrict__ out, int n) {
    int gt = blockIdx.x * blockDim.x + threadIdx.x;
    int node = gt >> 5;
    int lane = threadIdx.x & 31;
    if (node >= n) return;
    int start = g_rowptr[node];
    int cnt = g_cnt[node];
    float di = g_dinv[node];
    float acc = di * g_xw2[(long long)node * NCLS + lane];  // self loop
    for (int e = 0; e < cnt; e++) {
        int s = g_csr[start + e];
        float ds = g_dinv[s];
        acc = fmaf(ds, g_xw2[(long long)s * NCLS + lane], acc);
    }
    float v = fmaf(di, acc, b2[lane]);
    // log_softmax over 32 lanes
    float m = v;
#pragma unroll
    for (int o = 16; o > 0; o >>= 1) m = fmaxf(m, __shfl_xor_sync(0xffffffffu, m, o));
    float ex = __expf(v - m);
    float s = ex;
#pragma unroll
    for (int o = 16; o > 0; o >>= 1) s += __shfl_xor_sync(0xffffffffu, s, o);
    out[(long long)node * NCLS + lane] = v - m - logf(s);
}

// ---------------- launch ----------------
extern "C" void kernel_launch(void* const* d_in, const int* in_sizes, int n_in,
                              void* d_out, int out_size) {
    const float* X = (const float*)d_in[0];
    const void* EI = d_in[1];
    const float* W1 = (const float*)d_in[2];
    const float* b1 = (const float*)d_in[3];
    const float* W2 = (const float*)d_in[4];
    const float* b2 = (const float*)d_in[5];
    float* out = (float*)d_out;

    int n = in_sizes[0] / FIN;   // 100000
    int e = in_sizes[1] / 2;     // 800000

    k_detect<<<1, 32>>>(EI);
    k_zero<<<(n + 255) / 256, 256>>>(n);
    k_hist<<<(e + 255) / 256, 256>>>(EI, e);
    int scan_blocks = (n + 1023) / 1024;  // 98
    k_scan1<<<scan_blocks, 1024>>>(n);
    k_scan2<<<1, 128>>>(scan_blocks);
    k_scan3<<<scan_blocks, 1024>>>(n);
    k_scatter<<<(e + 255) / 256, 256>>>(EI, e);

    k_gemm1<<<(n + G1_BM - 1) / G1_BM, 256>>>(X, W1, n);
    k_agg1<<<(n * 32 + 255) / 256, 256>>>(b1, n);
    k_gemm2<<<(n + G2_BM - 1) / G2_BM, 256>>>(W2, n);
    k_agg2<<<(n * 32 + 255) / 256, 256>>>(b2, out, n);
}